// round 7
// baseline (speedup 1.0000x reference)
#include <cuda_runtime.h>
#include <math.h>

// CharRNN fused persistent kernel, round 7.
// B=512, L=1024, E=32, H=128, V=32.
// 256 CTAs x 256 threads, 2 batch rows/CTA, 2 CTAs/SM (16 warps/SM).
// i-dimension split 2-way: thread (g=tid>>7, j=tid&127) holds W_hh[i][j] for
// i in [64g, 64g+64) in 32 f32x2 regs, computes a half-column partial; a
// second barrier phase combines halves + tanh. Two bars/step:
//   period 1: A-partials(t) and logit-partials(t-1), both reading h(t-1)
//   period 2: combine->h(t);  logit reduce+STG for t-1
// Only h is double-buffered; partial buffers are single-buffered.

#define ULL unsigned long long

__device__ __forceinline__ ULL ffma2(ULL a, ULL b, ULL c) {
    ULL d;
    asm("fma.rn.f32x2 %0, %1, %2, %3;" : "=l"(d) : "l"(a), "l"(b), "l"(c));
    return d;
}
__device__ __forceinline__ ULL pack2(float lo, float hi) {
    ULL d;
    asm("mov.b64 %0, {%1, %2};" : "=l"(d) : "f"(lo), "f"(hi));
    return d;
}
__device__ __forceinline__ float sum2(ULL a) {
    float lo, hi;
    asm("mov.b64 {%0, %1}, %2;" : "=f"(lo), "=f"(hi) : "l"(a));
    return lo + hi;
}
// Stable fast tanh: 1 - 2/(exp(2x)+1).
__device__ __forceinline__ float fast_tanh(float x) {
    return 1.0f - __fdividef(2.0f, __expf(2.0f * x) + 1.0f);
}

__global__ void __launch_bounds__(256, 2) charrnn_kernel(
    const int*   __restrict__ x,      // [512][1024]
    const float* __restrict__ emb,    // [32][32]
    const float* __restrict__ Wxh,    // [32][128]
    const float* __restrict__ Whh,    // [128][128]
    const float* __restrict__ bh,     // [128]
    const float* __restrict__ Why,    // [128][32]
    const float* __restrict__ by_g,   // [32]
    float*       __restrict__ out)    // logits [512][1024][32] ++ hidden [512][128]
{
    __shared__ __align__(16) float  table[32 * 128];  // xh lookup: [token][j]
    __shared__ __align__(16) float  hbuf[2][2 * 128]; // hidden, ping-pong
    __shared__ __align__(8)  float2 papa[2 * 128];    // A-partials [r*128+j] = {g0,g1}
    __shared__ __align__(16) float  pbuf[2 * 256];    // logit partials [r][p][v]
    __shared__ int   xs[2 * 128];                     // token chunk [row][tloc]
    __shared__ float bys[32];

    const int tid = threadIdx.x;      // 0..255
    const int g   = tid >> 7;         // i-half selector
    const int j   = tid & 127;        // W_hh column / hidden index
    const int v   = tid & 31;         // logit vocab lane
    const int p   = tid >> 5;         // 0..7: logit i-range [16p,16p+16)
    const int r0  = blockIdx.x * 2;   // first batch row of this CTA

    // ---- one-time init ----
    for (int c = g * 16; c < g * 16 + 16; c++) {
        float s = bh[j];
        #pragma unroll 8
        for (int e = 0; e < 32; e++)
            s = fmaf(emb[c * 32 + e], Wxh[e * 128 + j], s);
        table[c * 128 + j] = s;
    }
    if (tid < 32) bys[tid] = by_g[tid];
    hbuf[1][tid] = 0.f;               // h_{-1} = 0 (parity buffer 1)

    // W_hy: thread (p,v) covers i-pairs k = 8p..8p+7
    ULL Wy[8];
    #pragma unroll
    for (int kk = 0; kk < 8; kk++) {
        int k = 8 * p + kk;
        Wy[kk] = pack2(Why[(2 * k) * 32 + v], Why[(2 * k + 1) * 32 + v]);
    }
    // W_hh half-column: i in [64g, 64g+64), i-pair packed
    ULL Wreg[32];
    #pragma unroll
    for (int k = 0; k < 32; k++) {
        int i0 = 64 * g + 2 * k;
        Wreg[k] = pack2(Whh[i0 * 128 + j], Whh[(i0 + 1) * 128 + j]);
    }

    for (int t = 0; t <= 1024; t++) {
        __syncthreads();                  // bar A: h(t-1) visible
        const int br = (t + 1) & 1;       // parity of h(t-1)
        const int bw = t & 1;             // parity of h(t)

        if (t < 1024) {
            const int tloc = t & 127;
            if (tloc == 0) {
                xs[tid] = x[(r0 + g) * 1024 + t + j];
                __syncthreads();
            }
            // ---- Phase A partials(t): half-i MACs for both rows ----
            const float* hb = hbuf[br];
            #pragma unroll
            for (int r = 0; r < 2; r++) {
                const ulonglong2* hp = (const ulonglong2*)(hb + r * 128 + 64 * g);
                ULL a0, a1 = 0ull;
                if (g == 0) {
                    const int c = xs[r * 128 + tloc];
                    a0 = pack2(table[c * 128 + j], 0.0f);
                } else {
                    a0 = 0ull;
                }
                #pragma unroll
                for (int kk = 0; kk < 16; kk++) {
                    ulonglong2 hh = hp[kk];
                    a0 = ffma2(hh.x, Wreg[2 * kk],     a0);
                    a1 = ffma2(hh.y, Wreg[2 * kk + 1], a1);
                }
                ((float*)&papa[r * 128 + j])[g] = sum2(a0) + sum2(a1);
            }
        }
        if (t >= 1) {
            // ---- Logit partials for step t-1 (reads h(t-1)) ----
            const float* hb = hbuf[br];
            #pragma unroll
            for (int r = 0; r < 2; r++) {
                const ulonglong2* hp = (const ulonglong2*)(hb + r * 128 + 16 * p);
                ULL s0 = 0ull, s1 = 0ull;
                #pragma unroll
                for (int q = 0; q < 4; q++) {
                    ulonglong2 hh = hp[q];
                    s0 = ffma2(hh.x, Wy[2 * q],     s0);
                    s1 = ffma2(hh.y, Wy[2 * q + 1], s1);
                }
                pbuf[r * 256 + p * 32 + v] = sum2(s0) + sum2(s1);
            }
        }

        __syncthreads();                  // bar B: partials visible

        if (t < 1024) {
            // ---- combine halves + tanh: thread (g,j) owns (row g, col j) ----
            float2 pp = papa[g * 128 + j];
            hbuf[bw][g * 128 + j] = fast_tanh(pp.x + pp.y);
        }
        if (t >= 1 && tid < 64) {
            // ---- logit reduce + store for step t-1 ----
            const int rr = tid >> 5;
            float s = bys[v];
            #pragma unroll
            for (int q = 0; q < 8; q++)
                s += pbuf[rr * 256 + q * 32 + v];
            out[(size_t)((r0 + rr) * 1024 + (t - 1)) * 32 + v] = s;
        }
    }

    // ---- final hidden: h(1023) lives in parity buffer 1 ----
    out[16777216u + (size_t)(r0 + g) * 128 + j] = hbuf[1][g * 128 + j];
}

extern "C" void kernel_launch(void* const* d_in, const int* in_sizes, int n_in,
                              void* d_out, int out_size) {
    (void)in_sizes; (void)n_in; (void)out_size;
    const int*   x   = (const int*)d_in[0];
    const float* emb = (const float*)d_in[1];
    const float* Wxh = (const float*)d_in[2];
    const float* Whh = (const float*)d_in[3];
    const float* bh  = (const float*)d_in[4];
    const float* Why = (const float*)d_in[5];
    const float* by  = (const float*)d_in[6];
    float* out = (float*)d_out;

    charrnn_kernel<<<256, 256>>>(x, emb, Wxh, Whh, bh, Why, by, out);
}

// round 9
// speedup vs baseline: 1.0023x; 1.0023x over previous
#include <cuda_runtime.h>
#include <math.h>

// CharRNN fused persistent kernel, round 8.
// B=512, L=1024, E=32, H=128, V=32.
// 256 CTAs x 256 threads, 2 batch rows/CTA, 2 CTAs/SM (16 warps/SM).
// Shuffle i-split: warp w covers columns j = 16w..16w+15; lane = (gi, jm),
// gi = lane>>4 selects i-half [64gi, 64gi+64). Thread holds half-column of
// W_hh (32 f32x2 regs), computes half-partials for BOTH rows; halves combined
// with shfl.bfly(16) + add (no barrier, no smem). Lane gi owns row gi's
// tanh + store. ONE __syncthreads per step. Pipeline (as R6):
//   period t: A(t) | logit-partials(t-1) | logit-reduce+STG(t-2)

#define ULL unsigned long long

__device__ __forceinline__ ULL ffma2(ULL a, ULL b, ULL c) {
    ULL d;
    asm("fma.rn.f32x2 %0, %1, %2, %3;" : "=l"(d) : "l"(a), "l"(b), "l"(c));
    return d;
}
__device__ __forceinline__ ULL pack2(float lo, float hi) {
    ULL d;
    asm("mov.b64 %0, {%1, %2};" : "=l"(d) : "f"(lo), "f"(hi));
    return d;
}
__device__ __forceinline__ float sum2(ULL a) {
    float lo, hi;
    asm("mov.b64 {%0, %1}, %2;" : "=f"(lo), "=f"(hi) : "l"(a));
    return lo + hi;
}
// Stable fast tanh: 1 - 2/(exp(2x)+1).
__device__ __forceinline__ float fast_tanh(float x) {
    return 1.0f - __fdividef(2.0f, __expf(2.0f * x) + 1.0f);
}

__global__ void __launch_bounds__(256, 2) charrnn_kernel(
    const int*   __restrict__ x,      // [512][1024]
    const float* __restrict__ emb,    // [32][32]
    const float* __restrict__ Wxh,    // [32][128]
    const float* __restrict__ Whh,    // [128][128]
    const float* __restrict__ bh,     // [128]
    const float* __restrict__ Why,    // [128][32]
    const float* __restrict__ by_g,   // [32]
    float*       __restrict__ out)    // logits [512][1024][32] ++ hidden [512][128]
{
    __shared__ __align__(16) float table[32 * 128];   // xh lookup: [token][j]
    __shared__ __align__(16) float hbuf[2][2 * 128];  // hidden, ping-pong
    __shared__ __align__(16) float pbuf[2][2 * 256];  // logit partials [r][p][v]
    __shared__ int   xs[2 * 128];                     // token chunk [row][tloc]
    __shared__ float bys[32];

    const int tid  = threadIdx.x;        // 0..255
    const int lane = tid & 31;
    const int w    = tid >> 5;           // warp 0..7
    const int gi   = lane >> 4;          // i-half selector (and row ownership)
    const int j    = w * 16 + (lane & 15); // W_hh column / hidden index
    const int v    = tid & 31;           // logit vocab lane
    const int p    = tid >> 5;           // logit i-range [16p, 16p+16)
    const int r0   = blockIdx.x * 2;     // first batch row of this CTA

    // ---- one-time init ----
    {
        const int jj = tid & 127;
        for (int c = (tid >> 7) * 16; c < (tid >> 7) * 16 + 16; c++) {
            float s = bh[jj];
            #pragma unroll 8
            for (int e = 0; e < 32; e++)
                s = fmaf(emb[c * 32 + e], Wxh[e * 128 + jj], s);
            table[c * 128 + jj] = s;
        }
    }
    if (tid < 32) bys[tid] = by_g[tid];
    if (tid < 256) { hbuf[1][tid & 255] = 0.f; }   // h_{-1} = 0 (parity 1)

    // W_hy: thread (p,v) covers i-pairs k = 8p..8p+7
    ULL Wy[8];
    #pragma unroll
    for (int kk = 0; kk < 8; kk++) {
        int k = 8 * p + kk;
        Wy[kk] = pack2(Why[(2 * k) * 32 + v], Why[(2 * k + 1) * 32 + v]);
    }
    // W_hh half-column: i in [64gi, 64gi+64), column j, i-pair packed
    ULL Wreg[32];
    #pragma unroll
    for (int k = 0; k < 32; k++) {
        int i0 = 64 * gi + 2 * k;
        Wreg[k] = pack2(Whh[i0 * 128 + j], Whh[(i0 + 1) * 128 + j]);
    }

    for (int t = 0; t < 1026; t++) {
        __syncthreads();                  // h(t-1), partials(t-2) visible
        const int bw = t & 1;             // parity of h(t) and reduce slot
        const int br = bw ^ 1;            // parity of h(t-1) and partial slot

        // ---- Phase A(t): h_t = tanh(xh[token_t] + h_{t-1} @ W_hh) ----
        if (t < 1024) {
            const int tloc = t & 127;
            if (tloc == 0) {
                xs[tid] = x[(r0 + (tid >> 7)) * 1024 + t + (tid & 127)];
                __syncthreads();
            }
            const float* hb = hbuf[br];
            const ulonglong2* hp0 = (const ulonglong2*)(hb + 64 * gi);        // row 0, my half
            const ulonglong2* hp1 = (const ulonglong2*)(hb + 128 + 64 * gi);  // row 1, my half
            ULL a0 = 0ull, a1 = 0ull, b0 = 0ull, b1 = 0ull;  // 4 chains, 16 deep
            #pragma unroll
            for (int k = 0; k < 16; k++) {
                ulonglong2 h0 = hp0[k];
                ulonglong2 h1 = hp1[k];
                a0 = ffma2(h0.x, Wreg[2 * k],     a0);
                b0 = ffma2(h1.x, Wreg[2 * k],     b0);
                a1 = ffma2(h0.y, Wreg[2 * k + 1], a1);
                b1 = ffma2(h1.y, Wreg[2 * k + 1], b1);
            }
            float s0 = sum2(a0) + sum2(a1);   // row-0 half-sum
            float s1 = sum2(b0) + sum2(b1);   // row-1 half-sum
            // combine i-halves across the bfly(16) partner — no smem, no bar
            float o0 = __shfl_xor_sync(0xffffffffu, s0, 16);
            float o1 = __shfl_xor_sync(0xffffffffu, s1, 16);
            float tot0 = s0 + o0;
            float tot1 = s1 + o1;
            // lane gi owns row gi for column j
            float mine = gi ? tot1 : tot0;
            const int c = xs[gi * 128 + tloc];
            mine += table[c * 128 + j];
            hbuf[bw][gi * 128 + j] = fast_tanh(mine);
        }

        // ---- Logit partials for step t-1 (reads h(t-1)) ----
        if (t >= 1 && t < 1025) {
            const float* hb = hbuf[br];
            float* pb = pbuf[br];
            #pragma unroll
            for (int r = 0; r < 2; r++) {
                const ulonglong2* hp = (const ulonglong2*)(hb + r * 128 + 16 * p);
                ULL s0 = 0ull, s1 = 0ull;
                #pragma unroll
                for (int q = 0; q < 4; q++) {
                    ulonglong2 hh = hp[q];
                    s0 = ffma2(hh.x, Wy[2 * q],     s0);
                    s1 = ffma2(hh.y, Wy[2 * q + 1], s1);
                }
                pb[r * 256 + p * 32 + v] = sum2(s0) + sum2(s1);
            }
        }

        // ---- Logit reduce + store for step t-2 ----
        if (t >= 2 && tid < 64) {
            const int rr = tid >> 5;
            const float* pb = pbuf[bw];      // partials for (t-2) have parity bw
            float s = bys[v];
            #pragma unroll
            for (int q = 0; q < 8; q++)
                s += pb[rr * 256 + q * 32 + v];
            out[(size_t)((r0 + rr) * 1024 + (t - 2)) * 32 + v] = s;
        }
    }

    // ---- final hidden: h(1023) has parity 1 ----
    out[16777216u + (size_t)(r0 + (tid >> 7)) * 128 + (tid & 127)] = hbuf[1][tid];
}

extern "C" void kernel_launch(void* const* d_in, const int* in_sizes, int n_in,
                              void* d_out, int out_size) {
    (void)in_sizes; (void)n_in; (void)out_size;
    const int*   x   = (const int*)d_in[0];
    const float* emb = (const float*)d_in[1];
    const float* Wxh = (const float*)d_in[2];
    const float* Whh = (const float*)d_in[3];
    const float* bh  = (const float*)d_in[4];
    const float* Why = (const float*)d_in[5];
    const float* by  = (const float*)d_in[6];
    float* out = (float*)d_out;

    charrnn_kernel<<<256, 256>>>(x, emb, Wxh, Whh, bh, Why, by, out);
}